// round 5
// baseline (speedup 1.0000x reference)
#include <cuda_runtime.h>
#include <cuda_bf16.h>
#include <cstdint>

#define N_NODES 100000
#define N_EDGES 3200000
#define N_GRAPHS 512
#define IN_DIM 29
#define HID 128
#define LAT 256

// ---------------- scratch (static device globals; no allocation) -----------
__device__ float g_hw[(size_t)N_NODES * HID];   // h @ W for current layer
__device__ float g_hA[(size_t)N_NODES * HID];   // ping
__device__ float g_hB[(size_t)N_NODES * HID];   // pong
__device__ float g_dis[N_NODES];                // deg^-1/2 (with self loop)
__device__ int   g_deg[N_NODES];
__device__ float g_ew[N_EDGES];                 // dis[src]*dis[dst]
__device__ float g_pool[N_GRAPHS * HID];
__device__ float g_cnt[N_GRAPHS];

// ---------------- init: zero all per-launch accumulators -------------------
__global__ void init_kernel() {
    int i = blockIdx.x * blockDim.x + threadIdx.x;
    if (i < N_NODES) g_deg[i] = 0;
    if (i < N_GRAPHS * HID) g_pool[i] = 0.f;
    if (i < N_GRAPHS) g_cnt[i] = 0.f;
}

// ---------------- edge prep: degree count (edge_index is int32) ------------
__global__ void edge_count_kernel(const int* __restrict__ ei) {
    int e = blockIdx.x * blockDim.x + threadIdx.x;
    if (e >= N_EDGES) return;
    int d = ei[N_EDGES + e];
    atomicAdd(&g_deg[d], 1);
}

__global__ void dis_kernel() {
    int i = blockIdx.x * blockDim.x + threadIdx.x;
    if (i >= N_NODES) return;
    g_dis[i] = rsqrtf((float)(g_deg[i] + 1));
}

__global__ void ew_kernel(const int* __restrict__ ei) {
    int e = blockIdx.x * blockDim.x + threadIdx.x;
    if (e >= N_EDGES) return;
    g_ew[e] = g_dis[ei[e]] * g_dis[ei[N_EDGES + e]];
}

// ---------------- GEMM: hw = (relu?)A @ W ; acc = hw*dis^2 + b -------------
// BM=64 rows/block, BN=128 (full width), BK=32 chunks, 256 threads,
// per-thread 4x8 register microtile.
#define BM 64
#define BKC 32
__global__ __launch_bounds__(256, 2)
void gemm_kernel(const float* __restrict__ A, int K, int relu_in,
                 const float* __restrict__ W, const float* __restrict__ b,
                 float* __restrict__ acc) {
    __shared__ float As[BKC][BM];      // 8 KB (k-major, transposed)
    __shared__ float Ws[BKC][HID];     // 16 KB

    int tid = threadIdx.x;
    int tx = tid & 15;    // column group: cols tx*8 .. tx*8+7
    int ty = tid >> 4;    // row group:    rows ty*4 .. ty*4+3
    int row0 = blockIdx.x * BM;

    float accr[4][8];
#pragma unroll
    for (int i = 0; i < 4; i++)
#pragma unroll
        for (int j = 0; j < 8; j++) accr[i][j] = 0.f;

    for (int k0 = 0; k0 < K; k0 += BKC) {
        int kc = min(BKC, K - k0);
        // load A chunk, transposed into As[k][row]
        for (int i = tid; i < BM * kc; i += 256) {
            int r = i / kc;
            int k = i - r * kc;
            int row = row0 + r;
            float v = 0.f;
            if (row < N_NODES) {
                v = A[(size_t)row * K + k0 + k];
                if (relu_in) v = fmaxf(v, 0.f);
            }
            As[k][r] = v;
        }
        // load W chunk (row-major contiguous)
        for (int i = tid; i < kc * HID; i += 256) {
            Ws[i >> 7][i & 127] = W[(size_t)k0 * HID + i];
        }
        __syncthreads();

        for (int k = 0; k < kc; k++) {
            float a[4], w[8];
#pragma unroll
            for (int i = 0; i < 4; i++) a[i] = As[k][ty * 4 + i];
#pragma unroll
            for (int j = 0; j < 8; j++) w[j] = Ws[k][tx * 8 + j];
#pragma unroll
            for (int i = 0; i < 4; i++)
#pragma unroll
                for (int j = 0; j < 8; j++) accr[i][j] += a[i] * w[j];
        }
        __syncthreads();
    }

    float bv[8];
#pragma unroll
    for (int j = 0; j < 8; j++) bv[j] = b[tx * 8 + j];

#pragma unroll
    for (int i = 0; i < 4; i++) {
        int row = row0 + ty * 4 + i;
        if (row < N_NODES) {
            float d = g_dis[row];
            float d2 = d * d;
            size_t base = (size_t)row * HID + tx * 8;
            float4 h0 = make_float4(accr[i][0], accr[i][1], accr[i][2], accr[i][3]);
            float4 h1 = make_float4(accr[i][4], accr[i][5], accr[i][6], accr[i][7]);
            *(float4*)(g_hw + base) = h0;
            *(float4*)(g_hw + base + 4) = h1;
            float4 a0 = make_float4(h0.x * d2 + bv[0], h0.y * d2 + bv[1],
                                    h0.z * d2 + bv[2], h0.w * d2 + bv[3]);
            float4 a1 = make_float4(h1.x * d2 + bv[4], h1.y * d2 + bv[5],
                                    h1.z * d2 + bv[6], h1.w * d2 + bv[7]);
            *(float4*)(acc + base) = a0;
            *(float4*)(acc + base + 4) = a1;
        }
    }
}

// ---------------- edge aggregation: acc[dst] += hw[src] * ew ----------------
// one warp per edge; lane covers 4 contiguous cols (float4 gather, 1 RED.128)
__global__ __launch_bounds__(256)
void edge_agg_kernel(const int* __restrict__ ei, float* __restrict__ acc) {
    long long t = (long long)blockIdx.x * blockDim.x + threadIdx.x;
    int e = (int)(t >> 5);
    if (e >= N_EDGES) return;
    int lane = (int)(t & 31);
    int s = ei[e];
    int d = ei[N_EDGES + e];
    float w = g_ew[e];
    float4 v = __ldg((const float4*)(g_hw + (size_t)s * HID) + lane);
    float4* ap = (float4*)(acc + (size_t)d * HID) + lane;
#if __CUDA_ARCH__ >= 900
    atomicAdd(ap, make_float4(v.x * w, v.y * w, v.z * w, v.w * w));
#else
    float* apf = (float*)ap;
    atomicAdd(apf + 0, v.x * w);
    atomicAdd(apf + 1, v.y * w);
    atomicAdd(apf + 2, v.z * w);
    atomicAdd(apf + 3, v.w * w);
#endif
}

// ---------------- pooling: run-length accumulate (batch is sorted int32) ----
__global__ __launch_bounds__(128)
void pool_kernel(const float* __restrict__ h, const int* __restrict__ batch) {
    int c = threadIdx.x;               // 0..127 column
    int n0 = blockIdx.x * 128;
    int nend = min(n0 + 128, N_NODES);
    if (n0 >= nend) return;
    int curg = batch[n0];
    float run = 0.f;
    int rl = 0;
    for (int n = n0; n < nend; n++) {
        int g = batch[n];
        if (g != curg) {
            atomicAdd(&g_pool[curg * HID + c], run);
            if (c == 0) atomicAdd(&g_cnt[curg], (float)rl);
            run = 0.f; rl = 0; curg = g;
        }
        run += fmaxf(h[(size_t)n * HID + c], 0.f);
        rl++;
    }
    atomicAdd(&g_pool[curg * HID + c], run);
    if (c == 0) atomicAdd(&g_cnt[curg], (float)rl);
}

// ---------------- heads: mu = pooled@Wmu+bmu ; logvar = pooled@Wlv+blv ------
__global__ __launch_bounds__(256)
void head_kernel(const float* __restrict__ Wmu, const float* __restrict__ bmu,
                 const float* __restrict__ Wlv, const float* __restrict__ blv,
                 float* __restrict__ out) {
    __shared__ float p[HID];
    int g = blockIdx.x;
    int j = threadIdx.x;       // 0..255
    if (j < HID) {
        float c = fmaxf(g_cnt[g], 1.f);
        p[j] = g_pool[g * HID + j] / c;
    }
    __syncthreads();
    float smu = bmu[j];
    float slv = blv[j];
#pragma unroll 4
    for (int k = 0; k < HID; k++) {
        float pk = p[k];
        smu += pk * Wmu[k * LAT + j];
        slv += pk * Wlv[k * LAT + j];
    }
    out[(size_t)g * LAT + j] = smu;
    out[(size_t)N_GRAPHS * LAT + (size_t)g * LAT + j] = slv;
}

// ---------------- launch ----------------------------------------------------
extern "C" void kernel_launch(void* const* d_in, const int* in_sizes, int n_in,
                              void* d_out, int out_size) {
    const float* x     = (const float*)d_in[0];
    const int*   ei    = (const int*)d_in[1];
    const int*   batch = (const int*)d_in[2];
    const float* W1  = (const float*)d_in[3];
    const float* b1  = (const float*)d_in[4];
    const float* W2  = (const float*)d_in[5];
    const float* b2  = (const float*)d_in[6];
    const float* W3  = (const float*)d_in[7];
    const float* b3  = (const float*)d_in[8];
    const float* Wmu = (const float*)d_in[9];
    const float* bmu = (const float*)d_in[10];
    const float* Wlv = (const float*)d_in[11];
    const float* blv = (const float*)d_in[12];
    float* out = (float*)d_out;

    float *pA, *pB;
    cudaGetSymbolAddress((void**)&pA, g_hA);
    cudaGetSymbolAddress((void**)&pB, g_hB);

    int nb_nodes = (N_NODES + 255) / 256;
    int nb_edges = (N_EDGES + 255) / 256;

    init_kernel<<<nb_nodes, 256>>>();
    edge_count_kernel<<<nb_edges, 256>>>(ei);
    dis_kernel<<<nb_nodes, 256>>>();
    ew_kernel<<<nb_edges, 256>>>(ei);

    int nb_gemm = (N_NODES + BM - 1) / BM;
    long long agg_threads = (long long)N_EDGES * 32;
    int nb_agg = (int)((agg_threads + 255) / 256);

    // layer 1: x (K=29) -> A
    gemm_kernel<<<nb_gemm, 256>>>(x, IN_DIM, 0, W1, b1, pA);
    edge_agg_kernel<<<nb_agg, 256>>>(ei, pA);
    // layer 2: relu(A) -> B
    gemm_kernel<<<nb_gemm, 256>>>(pA, HID, 1, W2, b2, pB);
    edge_agg_kernel<<<nb_agg, 256>>>(ei, pB);
    // layer 3: relu(B) -> A
    gemm_kernel<<<nb_gemm, 256>>>(pB, HID, 1, W3, b3, pA);
    edge_agg_kernel<<<nb_agg, 256>>>(ei, pA);

    pool_kernel<<<(N_NODES + 127) / 128, 128>>>(pA, batch);
    head_kernel<<<N_GRAPHS, 256>>>(Wmu, bmu, Wlv, blv, out);
}

// round 8
// speedup vs baseline: 2.0935x; 2.0935x over previous
#include <cuda_runtime.h>
#include <cuda_bf16.h>
#include <cstdint>

#define N_NODES 100000
#define N_EDGES 3200000
#define N_GRAPHS 512
#define IN_DIM 29
#define HID 128
#define LAT 256
#define NB_SCAN ((N_NODES + 255) / 256)   // 391

// ---------------- scratch (static device globals; no allocation) -----------
__device__ float g_hw[(size_t)N_NODES * HID];   // h @ W for current layer
__device__ float g_hA[(size_t)N_NODES * HID];   // layer output ping
__device__ float g_hB[(size_t)N_NODES * HID];   // layer output pong
__device__ float g_dis[N_NODES];                // deg^-1/2 (with self loop)
__device__ int   g_deg[N_NODES];
__device__ int   g_scan[N_NODES];               // block-local exclusive scan
__device__ int   g_bsum[NB_SCAN];
__device__ int   g_boff[NB_SCAN];
__device__ int   g_rowstart[N_NODES + 1];       // CSR row offsets (by dst)
__device__ int   g_cursor[N_NODES];
__device__ int2  g_csr[N_EDGES];                // (src, bitcast(weight))
__device__ float g_pool[N_GRAPHS * HID];
__device__ float g_cnt[N_GRAPHS];

// ---------------- init: zero per-launch accumulators -----------------------
__global__ void init_kernel() {
    int i = blockIdx.x * blockDim.x + threadIdx.x;
    if (i < N_NODES) g_deg[i] = 0;
    if (i < N_GRAPHS * HID) g_pool[i] = 0.f;
    if (i < N_GRAPHS) g_cnt[i] = 0.f;
}

// ---------------- edge prep: degree count (edge_index is int32) ------------
__global__ void edge_count_kernel(const int* __restrict__ ei) {
    int e = blockIdx.x * blockDim.x + threadIdx.x;
    if (e >= N_EDGES) return;
    atomicAdd(&g_deg[ei[N_EDGES + e]], 1);
}

__global__ void dis_kernel() {
    int i = blockIdx.x * blockDim.x + threadIdx.x;
    if (i >= N_NODES) return;
    g_dis[i] = rsqrtf((float)(g_deg[i] + 1));
}

// ---------------- CSR build: 3-pass scan + fill -----------------------------
__global__ void scanA_kernel() {
    __shared__ int s[256];
    int tid = threadIdx.x;
    int i = blockIdx.x * 256 + tid;
    int v = (i < N_NODES) ? g_deg[i] : 0;
    s[tid] = v;
    __syncthreads();
#pragma unroll
    for (int off = 1; off < 256; off <<= 1) {
        int t = (tid >= off) ? s[tid - off] : 0;
        __syncthreads();
        s[tid] += t;
        __syncthreads();
    }
    if (i < N_NODES) g_scan[i] = s[tid] - v;    // exclusive
    if (tid == 255) g_bsum[blockIdx.x] = s[255];
}

__global__ void scanB_kernel() {      // single block, 512 threads
    __shared__ int s[512];
    int tid = threadIdx.x;
    int v = (tid < NB_SCAN) ? g_bsum[tid] : 0;
    s[tid] = v;
    __syncthreads();
#pragma unroll
    for (int off = 1; off < 512; off <<= 1) {
        int t = (tid >= off) ? s[tid - off] : 0;
        __syncthreads();
        s[tid] += t;
        __syncthreads();
    }
    if (tid < NB_SCAN) g_boff[tid] = s[tid] - v;
}

__global__ void scanC_kernel() {
    int i = blockIdx.x * 256 + threadIdx.x;
    if (i < N_NODES) {
        int r = g_scan[i] + g_boff[blockIdx.x];
        g_rowstart[i] = r;
        g_cursor[i] = r;
    }
    if (i == 0) g_rowstart[N_NODES] = N_EDGES;
}

__global__ void csr_fill_kernel(const int* __restrict__ ei) {
    int e = blockIdx.x * blockDim.x + threadIdx.x;
    if (e >= N_EDGES) return;
    int s = ei[e];
    int d = ei[N_EDGES + e];
    float w = g_dis[s] * g_dis[d];
    int pos = atomicAdd(&g_cursor[d], 1);
    g_csr[pos] = make_int2(s, __float_as_int(w));
}

// ---------------- GEMM: g_hw = (relu?)A @ W ---------------------------------
#define BM 64
#define BKC 32
__global__ __launch_bounds__(256, 2)
void gemm_kernel(const float* __restrict__ A, int K, int relu_in,
                 const float* __restrict__ W) {
    __shared__ float As[BKC][BM];
    __shared__ float Ws[BKC][HID];

    int tid = threadIdx.x;
    int tx = tid & 15;    // cols tx*8 .. tx*8+7
    int ty = tid >> 4;    // rows ty*4 .. ty*4+3
    int row0 = blockIdx.x * BM;

    float accr[4][8];
#pragma unroll
    for (int i = 0; i < 4; i++)
#pragma unroll
        for (int j = 0; j < 8; j++) accr[i][j] = 0.f;

    for (int k0 = 0; k0 < K; k0 += BKC) {
        int kc = min(BKC, K - k0);
        for (int i = tid; i < BM * kc; i += 256) {
            int r = i / kc;
            int k = i - r * kc;
            int row = row0 + r;
            float v = 0.f;
            if (row < N_NODES) {
                v = A[(size_t)row * K + k0 + k];
                if (relu_in) v = fmaxf(v, 0.f);
            }
            As[k][r] = v;
        }
        for (int i = tid; i < kc * HID; i += 256) {
            Ws[i >> 7][i & 127] = W[(size_t)k0 * HID + i];
        }
        __syncthreads();

        for (int k = 0; k < kc; k++) {
            float a[4], w[8];
#pragma unroll
            for (int i = 0; i < 4; i++) a[i] = As[k][ty * 4 + i];
#pragma unroll
            for (int j = 0; j < 8; j++) w[j] = Ws[k][tx * 8 + j];
#pragma unroll
            for (int i = 0; i < 4; i++)
#pragma unroll
                for (int j = 0; j < 8; j++) accr[i][j] += a[i] * w[j];
        }
        __syncthreads();
    }

#pragma unroll
    for (int i = 0; i < 4; i++) {
        int row = row0 + ty * 4 + i;
        if (row < N_NODES) {
            size_t base = (size_t)row * HID + tx * 8;
            *(float4*)(g_hw + base) =
                make_float4(accr[i][0], accr[i][1], accr[i][2], accr[i][3]);
            *(float4*)(g_hw + base + 4) =
                make_float4(accr[i][4], accr[i][5], accr[i][6], accr[i][7]);
        }
    }
}

// ---------------- CSR aggregation: out[n] = sum_in hw[src]*w + hw[n]*d2 + b -
// one warp per destination node; lane owns 4 contiguous columns
__global__ __launch_bounds__(256)
void agg_csr_kernel(const float* __restrict__ b, float* __restrict__ out) {
    int warp = threadIdx.x >> 5;
    int lane = threadIdx.x & 31;
    int n = blockIdx.x * 8 + warp;
    if (n >= N_NODES) return;

    int p0 = g_rowstart[n];
    int p1 = g_rowstart[n + 1];

    // self-loop term
    float d = g_dis[n];
    float d2 = d * d;
    float4 hv = __ldg((const float4*)(g_hw + (size_t)n * HID) + lane);
    float4 bv = __ldg((const float4*)b + lane);
    float4 a = make_float4(hv.x * d2 + bv.x, hv.y * d2 + bv.y,
                           hv.z * d2 + bv.z, hv.w * d2 + bv.w);

#pragma unroll 4
    for (int p = p0; p < p1; p++) {
        int2 sw = __ldg(g_csr + p);
        float w = __int_as_float(sw.y);
        float4 v = __ldg((const float4*)(g_hw + (size_t)sw.x * HID) + lane);
        a.x += v.x * w;
        a.y += v.y * w;
        a.z += v.z * w;
        a.w += v.w * w;
    }
    ((float4*)(out + (size_t)n * HID))[lane] = a;
}

// ---------------- pooling: run-length accumulate (batch sorted int32) -------
__global__ __launch_bounds__(128)
void pool_kernel(const float* __restrict__ h, const int* __restrict__ batch) {
    int c = threadIdx.x;
    int n0 = blockIdx.x * 128;
    int nend = min(n0 + 128, N_NODES);
    if (n0 >= nend) return;
    int curg = batch[n0];
    float run = 0.f;
    int rl = 0;
    for (int n = n0; n < nend; n++) {
        int g = batch[n];
        if (g != curg) {
            atomicAdd(&g_pool[curg * HID + c], run);
            if (c == 0) atomicAdd(&g_cnt[curg], (float)rl);
            run = 0.f; rl = 0; curg = g;
        }
        run += fmaxf(h[(size_t)n * HID + c], 0.f);
        rl++;
    }
    atomicAdd(&g_pool[curg * HID + c], run);
    if (c == 0) atomicAdd(&g_cnt[curg], (float)rl);
}

// ---------------- heads -----------------------------------------------------
__global__ __launch_bounds__(256)
void head_kernel(const float* __restrict__ Wmu, const float* __restrict__ bmu,
                 const float* __restrict__ Wlv, const float* __restrict__ blv,
                 float* __restrict__ out) {
    __shared__ float p[HID];
    int g = blockIdx.x;
    int j = threadIdx.x;
    if (j < HID) {
        float c = fmaxf(g_cnt[g], 1.f);
        p[j] = g_pool[g * HID + j] / c;
    }
    __syncthreads();
    float smu = bmu[j];
    float slv = blv[j];
#pragma unroll 4
    for (int k = 0; k < HID; k++) {
        float pk = p[k];
        smu += pk * Wmu[k * LAT + j];
        slv += pk * Wlv[k * LAT + j];
    }
    out[(size_t)g * LAT + j] = smu;
    out[(size_t)N_GRAPHS * LAT + (size_t)g * LAT + j] = slv;
}

// ---------------- launch ----------------------------------------------------
extern "C" void kernel_launch(void* const* d_in, const int* in_sizes, int n_in,
                              void* d_out, int out_size) {
    const float* x     = (const float*)d_in[0];
    const int*   ei    = (const int*)d_in[1];
    const int*   batch = (const int*)d_in[2];
    const float* W1  = (const float*)d_in[3];
    const float* b1  = (const float*)d_in[4];
    const float* W2  = (const float*)d_in[5];
    const float* b2  = (const float*)d_in[6];
    const float* W3  = (const float*)d_in[7];
    const float* b3  = (const float*)d_in[8];
    const float* Wmu = (const float*)d_in[9];
    const float* bmu = (const float*)d_in[10];
    const float* Wlv = (const float*)d_in[11];
    const float* blv = (const float*)d_in[12];
    float* out = (float*)d_out;

    float *pA, *pB;
    cudaGetSymbolAddress((void**)&pA, g_hA);
    cudaGetSymbolAddress((void**)&pB, g_hB);

    int nb_nodes = (N_NODES + 255) / 256;
    int nb_edges = (N_EDGES + 255) / 256;

    init_kernel<<<nb_nodes, 256>>>();
    edge_count_kernel<<<nb_edges, 256>>>(ei);
    dis_kernel<<<nb_nodes, 256>>>();
    scanA_kernel<<<NB_SCAN, 256>>>();
    scanB_kernel<<<1, 512>>>();
    scanC_kernel<<<NB_SCAN, 256>>>();
    csr_fill_kernel<<<nb_edges, 256>>>(ei);

    int nb_gemm = (N_NODES + BM - 1) / BM;
    int nb_agg = (N_NODES + 7) / 8;

    // layer 1: x (K=29) -> hw -> A
    gemm_kernel<<<nb_gemm, 256>>>(x, IN_DIM, 0, W1);
    agg_csr_kernel<<<nb_agg, 256>>>(b1, pA);
    // layer 2: relu(A) -> hw -> B
    gemm_kernel<<<nb_gemm, 256>>>(pA, HID, 1, W2);
    agg_csr_kernel<<<nb_agg, 256>>>(b2, pB);
    // layer 3: relu(B) -> hw -> A
    gemm_kernel<<<nb_gemm, 256>>>(pB, HID, 1, W3);
    agg_csr_kernel<<<nb_agg, 256>>>(b3, pA);

    pool_kernel<<<(N_NODES + 127) / 128, 128>>>(pA, batch);
    head_kernel<<<N_GRAPHS, 256>>>(Wmu, bmu, Wlv, blv, out);
}

// round 9
// speedup vs baseline: 2.3904x; 1.1419x over previous
#include <cuda_runtime.h>
#include <cuda_bf16.h>
#include <cuda_fp16.h>
#include <cstdint>

#define N_NODES 100000
#define N_EDGES 3200000
#define N_GRAPHS 512
#define IN_DIM 29
#define HID 128
#define LAT 256
#define NB_SCAN ((N_NODES + 255) / 256)   // 391

// ---------------- scratch (static device globals; no allocation) -----------
__device__ __half g_hw16[(size_t)N_NODES * HID]; // h @ W (fp16) layers 2/3
__device__ float g_z[(size_t)N_NODES * IN_DIM];  // aggregated x (layer 1)
__device__ float g_hA[(size_t)N_NODES * HID];    // layer output ping
__device__ float g_hB[(size_t)N_NODES * HID];    // layer output pong
__device__ float g_dis[N_NODES];                 // deg^-1/2 (with self loop)
__device__ int   g_deg[N_NODES];
__device__ int   g_scan[N_NODES];
__device__ int   g_bsum[NB_SCAN];
__device__ int   g_boff[NB_SCAN];
__device__ int   g_rowstart[N_NODES + 1];        // CSR row offsets (by dst)
__device__ int   g_cursor[N_NODES];
__device__ int2  g_csr[N_EDGES];                 // (src, bitcast(weight))
__device__ float g_pool[N_GRAPHS * HID];
__device__ float g_cnt[N_GRAPHS];

// ---------------- init: zero per-launch accumulators -----------------------
__global__ void init_kernel() {
    int i = blockIdx.x * blockDim.x + threadIdx.x;
    if (i < N_NODES) g_deg[i] = 0;
    if (i < N_GRAPHS * HID) g_pool[i] = 0.f;
    if (i < N_GRAPHS) g_cnt[i] = 0.f;
}

// ---------------- edge prep: degree count (edge_index is int32) ------------
__global__ void edge_count_kernel(const int* __restrict__ ei) {
    int e = blockIdx.x * blockDim.x + threadIdx.x;
    if (e >= N_EDGES) return;
    atomicAdd(&g_deg[ei[N_EDGES + e]], 1);
}

__global__ void dis_kernel() {
    int i = blockIdx.x * blockDim.x + threadIdx.x;
    if (i >= N_NODES) return;
    g_dis[i] = rsqrtf((float)(g_deg[i] + 1));
}

// ---------------- CSR build: 3-pass scan + fill -----------------------------
__global__ void scanA_kernel() {
    __shared__ int s[256];
    int tid = threadIdx.x;
    int i = blockIdx.x * 256 + tid;
    int v = (i < N_NODES) ? g_deg[i] : 0;
    s[tid] = v;
    __syncthreads();
#pragma unroll
    for (int off = 1; off < 256; off <<= 1) {
        int t = (tid >= off) ? s[tid - off] : 0;
        __syncthreads();
        s[tid] += t;
        __syncthreads();
    }
    if (i < N_NODES) g_scan[i] = s[tid] - v;    // exclusive
    if (tid == 255) g_bsum[blockIdx.x] = s[255];
}

__global__ void scanB_kernel() {      // single block, 512 threads
    __shared__ int s[512];
    int tid = threadIdx.x;
    int v = (tid < NB_SCAN) ? g_bsum[tid] : 0;
    s[tid] = v;
    __syncthreads();
#pragma unroll
    for (int off = 1; off < 512; off <<= 1) {
        int t = (tid >= off) ? s[tid - off] : 0;
        __syncthreads();
        s[tid] += t;
        __syncthreads();
    }
    if (tid < NB_SCAN) g_boff[tid] = s[tid] - v;
}

__global__ void scanC_kernel() {
    int i = blockIdx.x * 256 + threadIdx.x;
    if (i < N_NODES) {
        int r = g_scan[i] + g_boff[blockIdx.x];
        g_rowstart[i] = r;
        g_cursor[i] = r;
    }
    if (i == 0) g_rowstart[N_NODES] = N_EDGES;
}

__global__ void csr_fill_kernel(const int* __restrict__ ei) {
    int e = blockIdx.x * blockDim.x + threadIdx.x;
    if (e >= N_EDGES) return;
    int s = ei[e];
    int d = ei[N_EDGES + e];
    float w = g_dis[s] * g_dis[d];
    int pos = atomicAdd(&g_cursor[d], 1);
    g_csr[pos] = make_int2(s, __float_as_int(w));
}

// ---------------- layer-1: z[n] = sum_in x[src]*w + x[n]*dis^2 (dim 29) -----
// one warp per destination node; lane < 29 owns one column of x
__global__ __launch_bounds__(256)
void agg_x_kernel(const float* __restrict__ x) {
    int warp = threadIdx.x >> 5;
    int lane = threadIdx.x & 31;
    int n = blockIdx.x * 8 + warp;
    if (n >= N_NODES) return;

    int p0 = g_rowstart[n];
    int p1 = g_rowstart[n + 1];
    float d = g_dis[n];
    float d2 = d * d;
    float acc = (lane < IN_DIM) ? x[(size_t)n * IN_DIM + lane] * d2 : 0.f;

#pragma unroll 4
    for (int p = p0; p < p1; p++) {
        int2 sw = __ldg(g_csr + p);
        float w = __int_as_float(sw.y);
        float v = (lane < IN_DIM) ? __ldg(x + (size_t)sw.x * IN_DIM + lane) : 0.f;
        acc += v * w;
    }
    if (lane < IN_DIM) g_z[(size_t)n * IN_DIM + lane] = acc;
}

// ---------------- GEMM core macro body --------------------------------------
#define BM 64
#define BKC 32

// GEMM with fp32 output + bias: out = A @ W + b  (layer 1: A = g_z, K=29)
__global__ __launch_bounds__(256, 2)
void gemm_bias_kernel(const float* __restrict__ A, int K,
                      const float* __restrict__ W, const float* __restrict__ b,
                      float* __restrict__ out) {
    __shared__ float As[BKC][BM];
    __shared__ float Ws[BKC][HID];

    int tid = threadIdx.x;
    int tx = tid & 15;
    int ty = tid >> 4;
    int row0 = blockIdx.x * BM;

    float accr[4][8];
#pragma unroll
    for (int i = 0; i < 4; i++)
#pragma unroll
        for (int j = 0; j < 8; j++) accr[i][j] = 0.f;

    for (int k0 = 0; k0 < K; k0 += BKC) {
        int kc = min(BKC, K - k0);
        for (int i = tid; i < BM * kc; i += 256) {
            int r = i / kc;
            int k = i - r * kc;
            int row = row0 + r;
            As[k][r] = (row < N_NODES) ? A[(size_t)row * K + k0 + k] : 0.f;
        }
        for (int i = tid; i < kc * HID; i += 256) {
            Ws[i >> 7][i & 127] = W[(size_t)k0 * HID + i];
        }
        __syncthreads();
        for (int k = 0; k < kc; k++) {
            float a[4], w[8];
#pragma unroll
            for (int i = 0; i < 4; i++) a[i] = As[k][ty * 4 + i];
#pragma unroll
            for (int j = 0; j < 8; j++) w[j] = Ws[k][tx * 8 + j];
#pragma unroll
            for (int i = 0; i < 4; i++)
#pragma unroll
                for (int j = 0; j < 8; j++) accr[i][j] += a[i] * w[j];
        }
        __syncthreads();
    }

    float bv[8];
#pragma unroll
    for (int j = 0; j < 8; j++) bv[j] = b[tx * 8 + j];

#pragma unroll
    for (int i = 0; i < 4; i++) {
        int row = row0 + ty * 4 + i;
        if (row < N_NODES) {
            size_t base = (size_t)row * HID + tx * 8;
            *(float4*)(out + base) = make_float4(accr[i][0] + bv[0], accr[i][1] + bv[1],
                                                 accr[i][2] + bv[2], accr[i][3] + bv[3]);
            *(float4*)(out + base + 4) = make_float4(accr[i][4] + bv[4], accr[i][5] + bv[5],
                                                     accr[i][6] + bv[6], accr[i][7] + bv[7]);
        }
    }
}

// GEMM with relu on input, fp16 output (no bias): g_hw16 = relu(A) @ W
__global__ __launch_bounds__(256, 2)
void gemm_h16_kernel(const float* __restrict__ A,
                     const float* __restrict__ W) {
    __shared__ float As[BKC][BM];
    __shared__ float Ws[BKC][HID];

    int tid = threadIdx.x;
    int tx = tid & 15;
    int ty = tid >> 4;
    int row0 = blockIdx.x * BM;

    float accr[4][8];
#pragma unroll
    for (int i = 0; i < 4; i++)
#pragma unroll
        for (int j = 0; j < 8; j++) accr[i][j] = 0.f;

    for (int k0 = 0; k0 < HID; k0 += BKC) {
        for (int i = tid; i < BM * BKC; i += 256) {
            int r = i >> 5;          // / BKC
            int k = i & 31;          // % BKC
            int row = row0 + r;
            float v = 0.f;
            if (row < N_NODES) v = fmaxf(A[(size_t)row * HID + k0 + k], 0.f);
            As[k][r] = v;
        }
        for (int i = tid; i < BKC * HID; i += 256) {
            Ws[i >> 7][i & 127] = W[(size_t)k0 * HID + i];
        }
        __syncthreads();
#pragma unroll
        for (int k = 0; k < BKC; k++) {
            float a[4], w[8];
#pragma unroll
            for (int i = 0; i < 4; i++) a[i] = As[k][ty * 4 + i];
#pragma unroll
            for (int j = 0; j < 8; j++) w[j] = Ws[k][tx * 8 + j];
#pragma unroll
            for (int i = 0; i < 4; i++)
#pragma unroll
                for (int j = 0; j < 8; j++) accr[i][j] += a[i] * w[j];
        }
        __syncthreads();
    }

#pragma unroll
    for (int i = 0; i < 4; i++) {
        int row = row0 + ty * 4 + i;
        if (row < N_NODES) {
            size_t base = (size_t)row * HID + tx * 8;   // 16B aligned (8 halves)
            __half2 p0 = __floats2half2_rn(accr[i][0], accr[i][1]);
            __half2 p1 = __floats2half2_rn(accr[i][2], accr[i][3]);
            __half2 p2 = __floats2half2_rn(accr[i][4], accr[i][5]);
            __half2 p3 = __floats2half2_rn(accr[i][6], accr[i][7]);
            uint4 u;
            u.x = *reinterpret_cast<unsigned*>(&p0);
            u.y = *reinterpret_cast<unsigned*>(&p1);
            u.z = *reinterpret_cast<unsigned*>(&p2);
            u.w = *reinterpret_cast<unsigned*>(&p3);
            *reinterpret_cast<uint4*>(g_hw16 + base) = u;
        }
    }
}

// ---------------- CSR agg (fp16 hw): out = sum hw16[src]*w + hw16[n]*d2 + b -
// one warp per destination node; lane owns 4 contiguous columns (8B fp16)
__global__ __launch_bounds__(256)
void agg_h16_kernel(const float* __restrict__ b, float* __restrict__ out) {
    int warp = threadIdx.x >> 5;
    int lane = threadIdx.x & 31;
    int n = blockIdx.x * 8 + warp;
    if (n >= N_NODES) return;

    int p0 = g_rowstart[n];
    int p1 = g_rowstart[n + 1];

    float d = g_dis[n];
    float d2 = d * d;
    uint2 hr = __ldg((const uint2*)(g_hw16 + (size_t)n * HID) + lane);
    float2 h01 = __half22float2(*reinterpret_cast<__half2*>(&hr.x));
    float2 h23 = __half22float2(*reinterpret_cast<__half2*>(&hr.y));
    float4 bv = __ldg((const float4*)b + lane);
    float4 a = make_float4(h01.x * d2 + bv.x, h01.y * d2 + bv.y,
                           h23.x * d2 + bv.z, h23.y * d2 + bv.w);

#pragma unroll 4
    for (int p = p0; p < p1; p++) {
        int2 sw = __ldg(g_csr + p);
        float w = __int_as_float(sw.y);
        uint2 vr = __ldg((const uint2*)(g_hw16 + (size_t)sw.x * HID) + lane);
        float2 v01 = __half22float2(*reinterpret_cast<__half2*>(&vr.x));
        float2 v23 = __half22float2(*reinterpret_cast<__half2*>(&vr.y));
        a.x += v01.x * w;
        a.y += v01.y * w;
        a.z += v23.x * w;
        a.w += v23.y * w;
    }
    ((float4*)(out + (size_t)n * HID))[lane] = a;
}

// ---------------- pooling: run-length accumulate (batch sorted int32) -------
__global__ __launch_bounds__(128)
void pool_kernel(const float* __restrict__ h, const int* __restrict__ batch) {
    int c = threadIdx.x;
    int n0 = blockIdx.x * 128;
    int nend = min(n0 + 128, N_NODES);
    if (n0 >= nend) return;
    int curg = batch[n0];
    float run = 0.f;
    int rl = 0;
    for (int n = n0; n < nend; n++) {
        int g = batch[n];
        if (g != curg) {
            atomicAdd(&g_pool[curg * HID + c], run);
            if (c == 0) atomicAdd(&g_cnt[curg], (float)rl);
            run = 0.f; rl = 0; curg = g;
        }
        run += fmaxf(h[(size_t)n * HID + c], 0.f);
        rl++;
    }
    atomicAdd(&g_pool[curg * HID + c], run);
    if (c == 0) atomicAdd(&g_cnt[curg], (float)rl);
}

// ---------------- heads -----------------------------------------------------
__global__ __launch_bounds__(256)
void head_kernel(const float* __restrict__ Wmu, const float* __restrict__ bmu,
                 const float* __restrict__ Wlv, const float* __restrict__ blv,
                 float* __restrict__ out) {
    __shared__ float p[HID];
    int g = blockIdx.x;
    int j = threadIdx.x;
    if (j < HID) {
        float c = fmaxf(g_cnt[g], 1.f);
        p[j] = g_pool[g * HID + j] / c;
    }
    __syncthreads();
    float smu = bmu[j];
    float slv = blv[j];
#pragma unroll 4
    for (int k = 0; k < HID; k++) {
        float pk = p[k];
        smu += pk * Wmu[k * LAT + j];
        slv += pk * Wlv[k * LAT + j];
    }
    out[(size_t)g * LAT + j] = smu;
    out[(size_t)N_GRAPHS * LAT + (size_t)g * LAT + j] = slv;
}

// ---------------- launch ----------------------------------------------------
extern "C" void kernel_launch(void* const* d_in, const int* in_sizes, int n_in,
                              void* d_out, int out_size) {
    const float* x     = (const float*)d_in[0];
    const int*   ei    = (const int*)d_in[1];
    const int*   batch = (const int*)d_in[2];
    const float* W1  = (const float*)d_in[3];
    const float* b1  = (const float*)d_in[4];
    const float* W2  = (const float*)d_in[5];
    const float* b2  = (const float*)d_in[6];
    const float* W3  = (const float*)d_in[7];
    const float* b3  = (const float*)d_in[8];
    const float* Wmu = (const float*)d_in[9];
    const float* bmu = (const float*)d_in[10];
    const float* Wlv = (const float*)d_in[11];
    const float* blv = (const float*)d_in[12];
    float* out = (float*)d_out;

    float *pA, *pB, *pZ;
    cudaGetSymbolAddress((void**)&pA, g_hA);
    cudaGetSymbolAddress((void**)&pB, g_hB);
    cudaGetSymbolAddress((void**)&pZ, g_z);

    int nb_nodes = (N_NODES + 255) / 256;
    int nb_edges = (N_EDGES + 255) / 256;

    init_kernel<<<nb_nodes, 256>>>();
    edge_count_kernel<<<nb_edges, 256>>>(ei);
    dis_kernel<<<nb_nodes, 256>>>();
    scanA_kernel<<<NB_SCAN, 256>>>();
    scanB_kernel<<<1, 512>>>();
    scanC_kernel<<<NB_SCAN, 256>>>();
    csr_fill_kernel<<<nb_edges, 256>>>(ei);

    int nb_gemm = (N_NODES + BM - 1) / BM;
    int nb_agg = (N_NODES + 7) / 8;

    // layer 1 (reordered): z = agg(x) ; h1 = z @ W1 + b1
    agg_x_kernel<<<nb_agg, 256>>>(x);
    gemm_bias_kernel<<<nb_gemm, 256>>>(pZ, IN_DIM, W1, b1, pA);
    // layer 2: hw16 = relu(h1) @ W2 ; h2 = agg(hw16) + b2
    gemm_h16_kernel<<<nb_gemm, 256>>>(pA, W2);
    agg_h16_kernel<<<nb_agg, 256>>>(b2, pB);
    // layer 3: hw16 = relu(h2) @ W3 ; h3 = agg(hw16) + b3
    gemm_h16_kernel<<<nb_gemm, 256>>>(pB, W3);
    agg_h16_kernel<<<nb_agg, 256>>>(b3, pA);

    pool_kernel<<<(N_NODES + 127) / 128, 128>>>(pA, batch);
    head_kernel<<<N_GRAPHS, 256>>>(Wmu, bmu, Wlv, blv, out);
}

// round 10
// speedup vs baseline: 3.1899x; 1.3345x over previous
#include <cuda_runtime.h>
#include <cuda_bf16.h>
#include <cuda_fp16.h>
#include <mma.h>
#include <cstdint>

using namespace nvcuda;

#define N_NODES 100000
#define N_EDGES 3200000
#define N_GRAPHS 512
#define IN_DIM 29
#define HID 128
#define LAT 256
#define NB_SCAN ((N_NODES + 255) / 256)   // 391

// ---------------- scratch (static device globals; no allocation) -----------
__device__ __half g_hw16[(size_t)N_NODES * HID];  // gemm output (pre-bias)
__device__ __half g_h16A[(size_t)N_NODES * HID];  // relu'd layer act ping
__device__ __half g_h16B[(size_t)N_NODES * HID];  // relu'd layer act pong
__device__ __half g_W2h[HID * HID];
__device__ __half g_W3h[HID * HID];
__device__ float g_z[(size_t)N_NODES * IN_DIM];   // aggregated x (layer 1)
__device__ float g_dis[N_NODES];                  // deg^-1/2 (with self loop)
__device__ int   g_deg[N_NODES];
__device__ int   g_scan[N_NODES];
__device__ int   g_bsum[NB_SCAN];
__device__ int   g_boff[NB_SCAN];
__device__ int   g_rowstart[N_NODES + 1];         // CSR row offsets (by dst)
__device__ int   g_cursor[N_NODES];
__device__ int2  g_csr[N_EDGES];                  // (src, bitcast(weight))
__device__ float g_pool[N_GRAPHS * HID];
__device__ float g_cnt[N_GRAPHS];

// ---------------- init: zero per-launch accumulators -----------------------
__global__ void init_kernel() {
    int i = blockIdx.x * blockDim.x + threadIdx.x;
    if (i < N_NODES) g_deg[i] = 0;
    if (i < N_GRAPHS * HID) g_pool[i] = 0.f;
    if (i < N_GRAPHS) g_cnt[i] = 0.f;
}

// ---------------- edge prep ------------------------------------------------
__global__ void edge_count_kernel(const int* __restrict__ ei) {
    int e = blockIdx.x * blockDim.x + threadIdx.x;
    if (e >= N_EDGES) return;
    atomicAdd(&g_deg[ei[N_EDGES + e]], 1);
}

__global__ void dis_kernel() {
    int i = blockIdx.x * blockDim.x + threadIdx.x;
    if (i >= N_NODES) return;
    g_dis[i] = rsqrtf((float)(g_deg[i] + 1));
}

__global__ void wconv_kernel(const float* __restrict__ W2,
                             const float* __restrict__ W3) {
    int i = blockIdx.x * blockDim.x + threadIdx.x;
    if (i < HID * HID) {
        g_W2h[i] = __float2half(W2[i]);
        g_W3h[i] = __float2half(W3[i]);
    }
}

// ---------------- CSR build: 3-pass scan + fill -----------------------------
__global__ void scanA_kernel() {
    __shared__ int s[256];
    int tid = threadIdx.x;
    int i = blockIdx.x * 256 + tid;
    int v = (i < N_NODES) ? g_deg[i] : 0;
    s[tid] = v;
    __syncthreads();
#pragma unroll
    for (int off = 1; off < 256; off <<= 1) {
        int t = (tid >= off) ? s[tid - off] : 0;
        __syncthreads();
        s[tid] += t;
        __syncthreads();
    }
    if (i < N_NODES) g_scan[i] = s[tid] - v;
    if (tid == 255) g_bsum[blockIdx.x] = s[255];
}

__global__ void scanB_kernel() {      // single block, 512 threads
    __shared__ int s[512];
    int tid = threadIdx.x;
    int v = (tid < NB_SCAN) ? g_bsum[tid] : 0;
    s[tid] = v;
    __syncthreads();
#pragma unroll
    for (int off = 1; off < 512; off <<= 1) {
        int t = (tid >= off) ? s[tid - off] : 0;
        __syncthreads();
        s[tid] += t;
        __syncthreads();
    }
    if (tid < NB_SCAN) g_boff[tid] = s[tid] - v;
}

__global__ void scanC_kernel() {
    int i = blockIdx.x * 256 + threadIdx.x;
    if (i < N_NODES) {
        int r = g_scan[i] + g_boff[blockIdx.x];
        g_rowstart[i] = r;
        g_cursor[i] = r;
    }
    if (i == 0) g_rowstart[N_NODES] = N_EDGES;
}

__global__ void csr_fill_kernel(const int* __restrict__ ei) {
    int e = blockIdx.x * blockDim.x + threadIdx.x;
    if (e >= N_EDGES) return;
    int s = ei[e];
    int d = ei[N_EDGES + e];
    float w = g_dis[s] * g_dis[d];
    int pos = atomicAdd(&g_cursor[d], 1);
    g_csr[pos] = make_int2(s, __float_as_int(w));
}

// ---------------- layer-1: z[n] = sum_in x[src]*w + x[n]*dis^2 (dim 29) -----
__global__ __launch_bounds__(256)
void agg_x_kernel(const float* __restrict__ x) {
    int warp = threadIdx.x >> 5;
    int lane = threadIdx.x & 31;
    int n = blockIdx.x * 8 + warp;
    if (n >= N_NODES) return;

    int p0 = g_rowstart[n];
    int p1 = g_rowstart[n + 1];
    float d = g_dis[n];
    float d2 = d * d;
    float acc = (lane < IN_DIM) ? x[(size_t)n * IN_DIM + lane] * d2 : 0.f;

#pragma unroll 4
    for (int p = p0; p < p1; p++) {
        int2 sw = __ldg(g_csr + p);
        float w = __int_as_float(sw.y);
        float v = (lane < IN_DIM) ? __ldg(x + (size_t)sw.x * IN_DIM + lane) : 0.f;
        acc += v * w;
    }
    if (lane < IN_DIM) g_z[(size_t)n * IN_DIM + lane] = acc;
}

// ---------------- layer-1 GEMM (FFMA, K=29): h16A = relu(z@W1 + b1) ---------
#define BM 64
#define BKC 32
__global__ __launch_bounds__(256, 2)
void gemm1_kernel(const float* __restrict__ A,
                  const float* __restrict__ W, const float* __restrict__ b,
                  __half* __restrict__ out) {
    __shared__ float As[BKC][BM];
    __shared__ float Ws[BKC][HID];

    const int K = IN_DIM;
    int tid = threadIdx.x;
    int tx = tid & 15;
    int ty = tid >> 4;
    int row0 = blockIdx.x * BM;

    float accr[4][8];
#pragma unroll
    for (int i = 0; i < 4; i++)
#pragma unroll
        for (int j = 0; j < 8; j++) accr[i][j] = 0.f;

    for (int k0 = 0; k0 < K; k0 += BKC) {
        int kc = min(BKC, K - k0);
        for (int i = tid; i < BM * kc; i += 256) {
            int r = i / kc;
            int k = i - r * kc;
            int row = row0 + r;
            As[k][r] = (row < N_NODES) ? A[(size_t)row * K + k0 + k] : 0.f;
        }
        for (int i = tid; i < kc * HID; i += 256) {
            Ws[i >> 7][i & 127] = W[(size_t)k0 * HID + i];
        }
        __syncthreads();
        for (int k = 0; k < kc; k++) {
            float a[4], w[8];
#pragma unroll
            for (int i = 0; i < 4; i++) a[i] = As[k][ty * 4 + i];
#pragma unroll
            for (int j = 0; j < 8; j++) w[j] = Ws[k][tx * 8 + j];
#pragma unroll
            for (int i = 0; i < 4; i++)
#pragma unroll
                for (int j = 0; j < 8; j++) accr[i][j] += a[i] * w[j];
        }
        __syncthreads();
    }

    float bv[8];
#pragma unroll
    for (int j = 0; j < 8; j++) bv[j] = b[tx * 8 + j];

#pragma unroll
    for (int i = 0; i < 4; i++) {
        int row = row0 + ty * 4 + i;
        if (row < N_NODES) {
            size_t base = (size_t)row * HID + tx * 8;
            float v[8];
#pragma unroll
            for (int j = 0; j < 8; j++) v[j] = fmaxf(accr[i][j] + bv[j], 0.f);
            __half2 h0 = __floats2half2_rn(v[0], v[1]);
            __half2 h1 = __floats2half2_rn(v[2], v[3]);
            __half2 h2 = __floats2half2_rn(v[4], v[5]);
            __half2 h3 = __floats2half2_rn(v[6], v[7]);
            uint4 u;
            u.x = *reinterpret_cast<unsigned*>(&h0);
            u.y = *reinterpret_cast<unsigned*>(&h1);
            u.z = *reinterpret_cast<unsigned*>(&h2);
            u.w = *reinterpret_cast<unsigned*>(&h3);
            *reinterpret_cast<uint4*>(out + base) = u;
        }
    }
}

// ---------------- tensor-core GEMM (layers 2/3): g_hw16 = A16 @ W16 ---------
// BM=64 rows/block, 256 threads = 8 warps; warp = (row strip 16, col half 64).
// A tile (64x128 fp16) resident; W streamed in two 64-row chunks.
#define TCBM 64
__global__ __launch_bounds__(256, 2)
void gemm_tc_kernel(const __half* __restrict__ A, const __half* __restrict__ W) {
    __shared__ alignas(16) __half As[TCBM * HID];   // 16 KB
    __shared__ alignas(16) __half Ws[64 * HID];     // 16 KB (reused as stage)

    int tid = threadIdx.x;
    int wid = tid >> 5;
    int lane = tid & 31;
    int rs = wid >> 1;          // 0..3 row strip (16 rows)
    int cs = wid & 1;           // 0..1 column half (64 cols)
    int row0 = blockIdx.x * TCBM;

    for (int i = tid; i < TCBM * 16; i += 256) {
        int r = i >> 4;
        int c = i & 15;
        uint4 v = make_uint4(0u, 0u, 0u, 0u);
        int row = row0 + r;
        if (row < N_NODES)
            v = *reinterpret_cast<const uint4*>(A + (size_t)row * HID + c * 8);
        *reinterpret_cast<uint4*>(As + r * HID + c * 8) = v;
    }

    wmma::fragment<wmma::accumulator, 16, 16, 16, float> acc[4];
#pragma unroll
    for (int j = 0; j < 4; j++) wmma::fill_fragment(acc[j], 0.f);

#pragma unroll
    for (int ch = 0; ch < 2; ch++) {
        __syncthreads();
        for (int i = tid; i < 64 * 16; i += 256) {
            int r = i >> 4;
            int c = i & 15;
            *reinterpret_cast<uint4*>(Ws + r * HID + c * 8) =
                *reinterpret_cast<const uint4*>(W + (size_t)(ch * 64 + r) * HID + c * 8);
        }
        __syncthreads();
#pragma unroll
        for (int k = 0; k < 4; k++) {
            wmma::fragment<wmma::matrix_a, 16, 16, 16, __half, wmma::row_major> af;
            wmma::load_matrix_sync(af, As + (rs * 16) * HID + ch * 64 + k * 16, HID);
#pragma unroll
            for (int j = 0; j < 4; j++) {
                wmma::fragment<wmma::matrix_b, 16, 16, 16, __half, wmma::row_major> bf;
                wmma::load_matrix_sync(bf, Ws + (k * 16) * HID + cs * 64 + j * 16, HID);
                wmma::mma_sync(acc[j], af, bf, acc[j]);
            }
        }
    }
    __syncthreads();            // all mma done; Ws free for staging

    float* stage = reinterpret_cast<float*>(Ws) + wid * 256;   // 1KB per warp
#pragma unroll
    for (int j = 0; j < 4; j++) {
        wmma::store_matrix_sync(stage, acc[j], 16, wmma::mem_row_major);
        __syncwarp();
        int r = lane >> 1;
        int c0 = (lane & 1) * 8;
        int row = row0 + rs * 16 + r;
        if (row < N_NODES) {
            float* sp = stage + r * 16 + c0;
            __half2 h0 = __floats2half2_rn(sp[0], sp[1]);
            __half2 h1 = __floats2half2_rn(sp[2], sp[3]);
            __half2 h2 = __floats2half2_rn(sp[4], sp[5]);
            __half2 h3 = __floats2half2_rn(sp[6], sp[7]);
            uint4 u;
            u.x = *reinterpret_cast<unsigned*>(&h0);
            u.y = *reinterpret_cast<unsigned*>(&h1);
            u.z = *reinterpret_cast<unsigned*>(&h2);
            u.w = *reinterpret_cast<unsigned*>(&h3);
            *reinterpret_cast<uint4*>(g_hw16 + (size_t)row * HID + cs * 64 + j * 16 + c0) = u;
        }
        __syncwarp();
    }
}

// ---------------- CSR agg: out16 = relu( sum hw16[src]*w + hw16[n]*d2 + b ) -
__global__ __launch_bounds__(256)
void agg_h16_kernel(const float* __restrict__ b, __half* __restrict__ out) {
    int warp = threadIdx.x >> 5;
    int lane = threadIdx.x & 31;
    int n = blockIdx.x * 8 + warp;
    if (n >= N_NODES) return;

    int p0 = g_rowstart[n];
    int p1 = g_rowstart[n + 1];

    float d = g_dis[n];
    float d2 = d * d;
    uint2 hr = __ldg((const uint2*)(g_hw16 + (size_t)n * HID) + lane);
    float2 h01 = __half22float2(*reinterpret_cast<__half2*>(&hr.x));
    float2 h23 = __half22float2(*reinterpret_cast<__half2*>(&hr.y));
    float4 bv = __ldg((const float4*)b + lane);
    float4 a = make_float4(h01.x * d2 + bv.x, h01.y * d2 + bv.y,
                           h23.x * d2 + bv.z, h23.y * d2 + bv.w);

#pragma unroll 4
    for (int p = p0; p < p1; p++) {
        int2 sw = __ldg(g_csr + p);
        float w = __int_as_float(sw.y);
        uint2 vr = __ldg((const uint2*)(g_hw16 + (size_t)sw.x * HID) + lane);
        float2 v01 = __half22float2(*reinterpret_cast<__half2*>(&vr.x));
        float2 v23 = __half22float2(*reinterpret_cast<__half2*>(&vr.y));
        a.x += v01.x * w;
        a.y += v01.y * w;
        a.z += v23.x * w;
        a.w += v23.y * w;
    }
    a.x = fmaxf(a.x, 0.f);
    a.y = fmaxf(a.y, 0.f);
    a.z = fmaxf(a.z, 0.f);
    a.w = fmaxf(a.w, 0.f);
    __half2 o0 = __floats2half2_rn(a.x, a.y);
    __half2 o1 = __floats2half2_rn(a.z, a.w);
    uint2 u;
    u.x = *reinterpret_cast<unsigned*>(&o0);
    u.y = *reinterpret_cast<unsigned*>(&o1);
    ((uint2*)(out + (size_t)n * HID))[lane] = u;
}

// ---------------- pooling (input already relu'd fp16) ------------------------
__global__ __launch_bounds__(128)
void pool_kernel(const __half* __restrict__ h, const int* __restrict__ batch) {
    int c = threadIdx.x;
    int n0 = blockIdx.x * 128;
    int nend = min(n0 + 128, N_NODES);
    if (n0 >= nend) return;
    int curg = batch[n0];
    float run = 0.f;
    int rl = 0;
    for (int n = n0; n < nend; n++) {
        int g = batch[n];
        if (g != curg) {
            atomicAdd(&g_pool[curg * HID + c], run);
            if (c == 0) atomicAdd(&g_cnt[curg], (float)rl);
            run = 0.f; rl = 0; curg = g;
        }
        run += __half2float(h[(size_t)n * HID + c]);
        rl++;
    }
    atomicAdd(&g_pool[curg * HID + c], run);
    if (c == 0) atomicAdd(&g_cnt[curg], (float)rl);
}

// ---------------- heads -----------------------------------------------------
__global__ __launch_bounds__(256)
void head_kernel(const float* __restrict__ Wmu, const float* __restrict__ bmu,
                 const float* __restrict__ Wlv, const float* __restrict__ blv,
                 float* __restrict__ out) {
    __shared__ float p[HID];
    int g = blockIdx.x;
    int j = threadIdx.x;
    if (j < HID) {
        float c = fmaxf(g_cnt[g], 1.f);
        p[j] = g_pool[g * HID + j] / c;
    }
    __syncthreads();
    float smu = bmu[j];
    float slv = blv[j];
#pragma unroll 4
    for (int k = 0; k < HID; k++) {
        float pk = p[k];
        smu += pk * Wmu[k * LAT + j];
        slv += pk * Wlv[k * LAT + j];
    }
    out[(size_t)g * LAT + j] = smu;
    out[(size_t)N_GRAPHS * LAT + (size_t)g * LAT + j] = slv;
}

// ---------------- launch ----------------------------------------------------
extern "C" void kernel_launch(void* const* d_in, const int* in_sizes, int n_in,
                              void* d_out, int out_size) {
    const float* x     = (const float*)d_in[0];
    const int*   ei    = (const int*)d_in[1];
    const int*   batch = (const int*)d_in[2];
    const float* W1  = (const float*)d_in[3];
    const float* b1  = (const float*)d_in[4];
    const float* W2  = (const float*)d_in[5];
    const float* b2  = (const float*)d_in[6];
    const float* W3  = (const float*)d_in[7];
    const float* b3  = (const float*)d_in[8];
    const float* Wmu = (const float*)d_in[9];
    const float* bmu = (const float*)d_in[10];
    const float* Wlv = (const float*)d_in[11];
    const float* blv = (const float*)d_in[12];
    float* out = (float*)d_out;

    float* pZ;
    __half *pA16, *pB16, *pW2h, *pW3h;
    cudaGetSymbolAddress((void**)&pZ, g_z);
    cudaGetSymbolAddress((void**)&pA16, g_h16A);
    cudaGetSymbolAddress((void**)&pB16, g_h16B);
    cudaGetSymbolAddress((void**)&pW2h, g_W2h);
    cudaGetSymbolAddress((void**)&pW3h, g_W3h);

    int nb_nodes = (N_NODES + 255) / 256;
    int nb_edges = (N_EDGES + 255) / 256;

    init_kernel<<<nb_nodes, 256>>>();
    edge_count_kernel<<<nb_edges, 256>>>(ei);
    dis_kernel<<<nb_nodes, 256>>>();
    wconv_kernel<<<(HID * HID + 255) / 256, 256>>>(W2, W3);
    scanA_kernel<<<NB_SCAN, 256>>>();
    scanB_kernel<<<1, 512>>>();
    scanC_kernel<<<NB_SCAN, 256>>>();
    csr_fill_kernel<<<nb_edges, 256>>>(ei);

    int nb_gemm1 = (N_NODES + BM - 1) / BM;
    int nb_gtc = (N_NODES + TCBM - 1) / TCBM;
    int nb_agg = (N_NODES + 7) / 8;

    // layer 1 (reordered): z = agg(x) ; h16A = relu(z @ W1 + b1)
    agg_x_kernel<<<nb_agg, 256>>>(x);
    gemm1_kernel<<<nb_gemm1, 256>>>(pZ, W1, b1, pA16);
    // layer 2: hw16 = h16A @ W2 ; h16B = relu(agg(hw16) + b2)
    gemm_tc_kernel<<<nb_gtc, 256>>>(pA16, pW2h);
    agg_h16_kernel<<<nb_agg, 256>>>(b2, pB16);
    // layer 3: hw16 = h16B @ W3 ; h16A = relu(agg(hw16) + b3)
    gemm_tc_kernel<<<nb_gtc, 256>>>(pB16, pW3h);
    agg_h16_kernel<<<nb_agg, 256>>>(b3, pA16);

    pool_kernel<<<(N_NODES + 127) / 128, 128>>>(pA16, batch);
    head_kernel<<<N_GRAPHS, 256>>>(Wmu, bmu, Wlv, blv, out);
}